// round 7
// baseline (speedup 1.0000x reference)
#include <cuda_runtime.h>
#include <cuda_fp16.h>
#include <mma.h>
#include <cstdint>
#include <cstddef>

using namespace nvcuda;

// Problem constants
constexpr int BATCH = 128;
constexpr int CMAX  = 272;
constexpr int TLEN  = 512;
constexpr int D1    = 320;
constexpr int NSUBJ = 8;
constexpr int CPAD  = 288;   // 9 * 32, zero-padded channel dim

// fp16 scratch (conversion done once in a pre-pass)
__device__ __half Xh[(size_t)BATCH * CPAD * TLEN];  // 37.7 MB
__device__ __half Wh[(size_t)NSUBJ * D1 * CPAD];    // 1.5 MB

// ---------------- pre-convert kernel ----------------
constexpr int64_t NXV = (int64_t)BATCH * CPAD * TLEN / 8;  // 8-half vectors
constexpr int64_t NWV = (int64_t)NSUBJ * D1 * CPAD / 8;

__global__ __launch_bounds__(256)
void convert_kernel(const float* __restrict__ X, const float* __restrict__ W)
{
    const int64_t i = (int64_t)blockIdx.x * blockDim.x + threadIdx.x;
    if (i < NXV) {
        const int64_t h0 = i * 8;
        const int b   = (int)(h0 / ((int64_t)CPAD * TLEN));
        const int rem = (int)(h0 % ((int64_t)CPAD * TLEN));
        const int c   = rem / TLEN;
        const int t   = rem % TLEN;
        __half2 o[4] = {};
        if (c < CMAX) {
            const float4* src = reinterpret_cast<const float4*>(
                X + ((int64_t)b * CMAX + c) * TLEN + t);
            float4 v0 = src[0], v1 = src[1];
            o[0] = __floats2half2_rn(v0.x, v0.y);
            o[1] = __floats2half2_rn(v0.z, v0.w);
            o[2] = __floats2half2_rn(v1.x, v1.y);
            o[3] = __floats2half2_rn(v1.z, v1.w);
        }
        *reinterpret_cast<uint4*>(&Xh[h0]) = *reinterpret_cast<const uint4*>(o);
    } else if (i < NXV + NWV) {
        const int64_t h0 = (i - NXV) * 8;
        const int sd = (int)(h0 / CPAD);   // s*D1 + d
        const int c  = (int)(h0 % CPAD);   // multiple of 8; 272 % 8 == 0
        __half2 o[4] = {};
        if (c < CMAX) {
            const float4* src = reinterpret_cast<const float4*>(
                W + (int64_t)sd * CMAX + c);
            float4 v0 = src[0], v1 = src[1];
            o[0] = __floats2half2_rn(v0.x, v0.y);
            o[1] = __floats2half2_rn(v0.z, v0.w);
            o[2] = __floats2half2_rn(v1.x, v1.y);
            o[3] = __floats2half2_rn(v1.z, v1.w);
        }
        *reinterpret_cast<uint4*>(&Wh[h0]) = *reinterpret_cast<const uint4*>(o);
    }
}

// ---------------- GEMM kernel ----------------
constexpr int BM = 64;
constexpr int BN = 256;
constexpr int BK = 32;
constexpr int STAGES = 4;
constexpr int NIT = CPAD / BK;   // 9, no predicates
constexpr int AST = BK + 8;      // 40 halves
constexpr int BST = BN + 8;      // 264 halves
constexpr int A_HALVES = BM * AST;   // 2560
constexpr int B_HALVES = BK * BST;   // 8448
constexpr int STAGE_HALVES = A_HALVES + B_HALVES;        // 11008
constexpr int SMEM_BYTES = STAGES * STAGE_HALVES * 2;    // 88064

__device__ __forceinline__ void cp_async16(void* smem_dst, const void* gmem_src) {
    unsigned sm = (unsigned)__cvta_generic_to_shared(smem_dst);
    asm volatile("cp.async.cg.shared.global [%0], [%1], 16;\n" :: "r"(sm), "l"(gmem_src));
}
__device__ __forceinline__ void cp_commit() { asm volatile("cp.async.commit_group;\n"); }
template <int N>
__device__ __forceinline__ void cp_wait() { asm volatile("cp.async.wait_group %0;\n" :: "n"(N)); }

__global__ __launch_bounds__(256, 2)
void sbconv_wmma_kernel(const int* __restrict__ sidx, float* __restrict__ out)
{
    extern __shared__ __half smem[];

    const int tid = threadIdx.x;
    const int b   = blockIdx.z;
    const int d0  = blockIdx.y * BM;
    const int t0  = blockIdx.x * BN;

    const int s = __ldg(&sidx[b]);
    const __half* Wp = Wh + ((size_t)s * D1 + d0) * CPAD;  // [BM, CPAD]
    const __half* Xp = Xh + (size_t)b * CPAD * TLEN + t0;  // [CPAD, TLEN]

    const int wid = tid >> 5;
    const int wm  = wid >> 2;   // 0..1  d-direction (32 rows each)
    const int wn  = wid & 3;    // 0..3  t-direction (64 cols each)

    // cp.async mappings
    const int a_row = tid >> 2;          // 0..63
    const int a_col = (tid & 3) * 8;     // halves: 0,8,16,24 (1 x 16B each)
    const int b_row = tid >> 3;          // 0..31
    const int b_col = (tid & 7) * 32;    // halves: 4 x 16B contiguous

    auto stageA = [&](int it, int slot) {
        __half* As = smem + slot * STAGE_HALVES;
        const __half* src = Wp + (size_t)a_row * CPAD + it * BK + a_col;
        cp_async16(&As[a_row * AST + a_col], src);
    };
    auto stageB = [&](int it, int slot) {
        __half* Bs = smem + slot * STAGE_HALVES + A_HALVES;
        const __half* src = Xp + (size_t)(it * BK + b_row) * TLEN + b_col;
        #pragma unroll
        for (int j = 0; j < 4; ++j)
            cp_async16(&Bs[b_row * BST + b_col + j * 8], src + j * 8);
    };

    wmma::fragment<wmma::accumulator, 16, 16, 16, float> acc[2][4];
    #pragma unroll
    for (int i = 0; i < 2; ++i)
        #pragma unroll
        for (int j = 0; j < 4; ++j)
            wmma::fill_fragment(acc[i][j], 0.0f);

    // Prologue: fill STAGES-1 stages
    #pragma unroll
    for (int st = 0; st < STAGES - 1; ++st) {
        stageA(st, st);
        stageB(st, st);
        cp_commit();
    }

    #pragma unroll 1
    for (int it = 0; it < NIT; ++it) {
        cp_wait<STAGES - 2>();
        __syncthreads();
        // Single barrier per iter. Safe: the prefetch below writes slot
        // (it+STAGES-1)%STAGES == (it-1)%STAGES, whose readers (compute
        // at iter it-1) are ordered before it by THIS barrier; the slot
        // being read now (it%STAGES) is never written this iteration.

        if (it + STAGES - 1 < NIT) {
            const int nslot = (it + STAGES - 1) % STAGES;
            stageA(it + STAGES - 1, nslot);
            stageB(it + STAGES - 1, nslot);
        }
        cp_commit();   // uniform group count even when empty

        const int slot = it % STAGES;
        const __half* As = smem + slot * STAGE_HALVES;
        const __half* Bs = As + A_HALVES;

        // Hoist all fragment loads for both k-halves, then the MMA bursts.
        wmma::fragment<wmma::matrix_a, 16, 16, 16, __half, wmma::row_major> af0[2], af1[2];
        wmma::fragment<wmma::matrix_b, 16, 16, 16, __half, wmma::row_major> bf0[4];
        #pragma unroll
        for (int i = 0; i < 2; ++i) {
            wmma::load_matrix_sync(af0[i], &As[(wm * 32 + i * 16) * AST + 0], AST);
            wmma::load_matrix_sync(af1[i], &As[(wm * 32 + i * 16) * AST + 16], AST);
        }
        #pragma unroll
        for (int j = 0; j < 4; ++j)
            wmma::load_matrix_sync(bf0[j], &Bs[0 * BST + wn * 64 + j * 16], BST);
        #pragma unroll
        for (int i = 0; i < 2; ++i)
            #pragma unroll
            for (int j = 0; j < 4; ++j)
                wmma::mma_sync(acc[i][j], af0[i], bf0[j], acc[i][j]);

        wmma::fragment<wmma::matrix_b, 16, 16, 16, __half, wmma::row_major> bf1[4];
        #pragma unroll
        for (int j = 0; j < 4; ++j)
            wmma::load_matrix_sync(bf1[j], &Bs[16 * BST + wn * 64 + j * 16], BST);
        #pragma unroll
        for (int i = 0; i < 2; ++i)
            #pragma unroll
            for (int j = 0; j < 4; ++j)
                wmma::mma_sync(acc[i][j], af1[i], bf1[j], acc[i][j]);
    }

    // Epilogue: warp writes its 32x64 tile
    #pragma unroll
    for (int i = 0; i < 2; ++i)
        #pragma unroll
        for (int j = 0; j < 4; ++j) {
            float* op = out + ((size_t)b * D1 + d0 + wm * 32 + i * 16) * TLEN
                            + t0 + wn * 64 + j * 16;
            wmma::store_matrix_sync(op, acc[i][j], TLEN, wmma::mem_row_major);
        }
}

extern "C" void kernel_launch(void* const* d_in, const int* in_sizes, int n_in,
                              void* d_out, int out_size)
{
    const float* X    = (const float*)d_in[0];  // [B, CMAX, T]
    const int*   sidx = (const int*)  d_in[1];  // [B]
    const float* W    = (const float*)d_in[2];  // [NS, D1, CMAX]
    float*       out  = (float*)d_out;          // [B, D1, T]

    // Pass 1: fp32 -> fp16 conversion (X once, W once)
    const int64_t total = NXV + NWV;
    const int cblocks = (int)((total + 255) / 256);
    convert_kernel<<<cblocks, 256>>>(X, W);

    // Pass 2: fp16 tensor-core GEMM
    static bool attr_set = false;
    if (!attr_set) {
        cudaFuncSetAttribute(sbconv_wmma_kernel,
                             cudaFuncAttributeMaxDynamicSharedMemorySize, SMEM_BYTES);
        attr_set = true;
    }
    dim3 grid(TLEN / BN, D1 / BM, BATCH);  // (2, 5, 128)
    sbconv_wmma_kernel<<<grid, 256, SMEM_BYTES>>>(sidx, out);
}

// round 9
// speedup vs baseline: 1.5089x; 1.5089x over previous
#include <cuda_runtime.h>
#include <cuda_fp16.h>
#include <mma.h>
#include <cstdint>
#include <cstddef>

using namespace nvcuda;

// Problem constants
constexpr int BATCH = 128;
constexpr int CMAX  = 272;
constexpr int TLEN  = 512;
constexpr int D1    = 320;
constexpr int NSUBJ = 8;
constexpr int CPAD  = 288;   // 9 * 32, zero-padded channel dim

// fp16 scratch (conversion done once in a pre-pass)
__device__ __half Xh[(size_t)BATCH * CPAD * TLEN];  // 37.7 MB
__device__ __half Wh[(size_t)NSUBJ * D1 * CPAD];    // 1.5 MB

// ---------------- pre-convert kernel ----------------
constexpr int64_t NXV = (int64_t)BATCH * CPAD * TLEN / 8;  // 8-half vectors
constexpr int64_t NWV = (int64_t)NSUBJ * D1 * CPAD / 8;

__global__ __launch_bounds__(256)
void convert_kernel(const float* __restrict__ X, const float* __restrict__ W)
{
    const int64_t i = (int64_t)blockIdx.x * blockDim.x + threadIdx.x;
    if (i < NXV) {
        const int64_t h0 = i * 8;
        const int b   = (int)(h0 / ((int64_t)CPAD * TLEN));
        const int rem = (int)(h0 % ((int64_t)CPAD * TLEN));
        const int c   = rem / TLEN;
        const int t   = rem % TLEN;
        __half2 o[4] = {};
        if (c < CMAX) {
            const float4* src = reinterpret_cast<const float4*>(
                X + ((int64_t)b * CMAX + c) * TLEN + t);
            float4 v0 = src[0], v1 = src[1];
            o[0] = __floats2half2_rn(v0.x, v0.y);
            o[1] = __floats2half2_rn(v0.z, v0.w);
            o[2] = __floats2half2_rn(v1.x, v1.y);
            o[3] = __floats2half2_rn(v1.z, v1.w);
        }
        *reinterpret_cast<uint4*>(&Xh[h0]) = *reinterpret_cast<const uint4*>(o);
    } else if (i < NXV + NWV) {
        const int64_t h0 = (i - NXV) * 8;
        const int sd = (int)(h0 / CPAD);   // s*D1 + d
        const int c  = (int)(h0 % CPAD);   // multiple of 8; 272 % 8 == 0
        __half2 o[4] = {};
        if (c < CMAX) {
            const float4* src = reinterpret_cast<const float4*>(
                W + (int64_t)sd * CMAX + c);
            float4 v0 = src[0], v1 = src[1];
            o[0] = __floats2half2_rn(v0.x, v0.y);
            o[1] = __floats2half2_rn(v0.z, v0.w);
            o[2] = __floats2half2_rn(v1.x, v1.y);
            o[3] = __floats2half2_rn(v1.z, v1.w);
        }
        *reinterpret_cast<uint4*>(&Wh[h0]) = *reinterpret_cast<const uint4*>(o);
    }
}

// ---------------- GEMM kernel ----------------
// 128-thread CTAs for 4 CTAs/SM: 4 independent pipeline domains per SM.
constexpr int BM = 64;
constexpr int BN = 128;
constexpr int BK = 32;
constexpr int STAGES = 3;
constexpr int NIT = CPAD / BK;   // 9, no predicates
constexpr int AST = BK + 8;      // 40 halves
constexpr int BST = BN + 8;      // 136 halves
constexpr int A_HALVES = BM * AST;   // 2560
constexpr int B_HALVES = BK * BST;   // 4352
constexpr int STAGE_HALVES = A_HALVES + B_HALVES;   // 6912
// total smem = 3 * 6912 * 2 = 41472 B < 48 KB -> static shared, no attribute.

__device__ __forceinline__ void cp_async16(void* smem_dst, const void* gmem_src) {
    unsigned sm = (unsigned)__cvta_generic_to_shared(smem_dst);
    asm volatile("cp.async.ca.shared.global [%0], [%1], 16;\n" :: "r"(sm), "l"(gmem_src));
}
__device__ __forceinline__ void cp_commit() { asm volatile("cp.async.commit_group;\n"); }
template <int N>
__device__ __forceinline__ void cp_wait() { asm volatile("cp.async.wait_group %0;\n" :: "n"(N)); }

__global__ __launch_bounds__(128, 4)
void sbconv_wmma_kernel(const int* __restrict__ sidx, float* __restrict__ out)
{
    __shared__ __half smem[STAGES * STAGE_HALVES];

    const int tid = threadIdx.x;
    const int b   = blockIdx.z;
    const int d0  = blockIdx.y * BM;
    const int t0  = blockIdx.x * BN;

    const int s = __ldg(&sidx[b]);
    const __half* Wp = Wh + ((size_t)s * D1 + d0) * CPAD;  // [BM, CPAD]
    const __half* Xp = Xh + (size_t)b * CPAD * TLEN + t0;  // [CPAD, TLEN]

    const int wid = tid >> 5;   // 0..3
    const int wm  = wid >> 1;   // 0..1  d-direction (32 rows each)
    const int wn  = wid & 1;    // 0..1  t-direction (64 cols each)

    // cp.async mappings (128 threads)
    const int a_row = tid >> 2;          // 0..31 (2 passes -> 64 rows)
    const int a_col = (tid & 3) * 8;     // halves: 0,8,16,24
    const int b_row = tid >> 2;          // 0..31
    const int b_col = (tid & 3) * 32;    // halves: 4 x 16B contiguous

    auto stageA = [&](int it, int slot) {
        __half* As = smem + slot * STAGE_HALVES;
        #pragma unroll
        for (int p = 0; p < 2; ++p) {
            const int row = p * 32 + a_row;
            cp_async16(&As[row * AST + a_col],
                       Wp + (size_t)row * CPAD + it * BK + a_col);
        }
    };
    auto stageB = [&](int it, int slot) {
        __half* Bs = smem + slot * STAGE_HALVES + A_HALVES;
        const __half* src = Xp + (size_t)(it * BK + b_row) * TLEN + b_col;
        #pragma unroll
        for (int j = 0; j < 4; ++j)
            cp_async16(&Bs[b_row * BST + b_col + j * 8], src + j * 8);
    };

    wmma::fragment<wmma::accumulator, 16, 16, 16, float> acc[2][4];
    #pragma unroll
    for (int i = 0; i < 2; ++i)
        #pragma unroll
        for (int j = 0; j < 4; ++j)
            wmma::fill_fragment(acc[i][j], 0.0f);

    // Prologue: fill STAGES-1 stages
    #pragma unroll
    for (int st = 0; st < STAGES - 1; ++st) {
        stageA(st, st);
        stageB(st, st);
        cp_commit();
    }

    #pragma unroll 1
    for (int it = 0; it < NIT; ++it) {
        cp_wait<STAGES - 2>();
        __syncthreads();
        // Single barrier per iter. Safe: the prefetch below writes slot
        // (it+STAGES-1)%STAGES == (it-1)%STAGES, whose readers (compute
        // at iter it-1) are ordered before it by THIS barrier; the slot
        // being read now (it%STAGES) is never written this iteration.

        if (it + STAGES - 1 < NIT) {
            const int nslot = (it + STAGES - 1) % STAGES;
            stageA(it + STAGES - 1, nslot);
            stageB(it + STAGES - 1, nslot);
        }
        cp_commit();   // uniform group count even when empty

        const int slot = it % STAGES;
        const __half* As = smem + slot * STAGE_HALVES;
        const __half* Bs = As + A_HALVES;

        #pragma unroll
        for (int kk = 0; kk < BK; kk += 16) {
            wmma::fragment<wmma::matrix_a, 16, 16, 16, __half, wmma::row_major> af[2];
            wmma::fragment<wmma::matrix_b, 16, 16, 16, __half, wmma::row_major> bf[4];
            #pragma unroll
            for (int i = 0; i < 2; ++i)
                wmma::load_matrix_sync(af[i], &As[(wm * 32 + i * 16) * AST + kk], AST);
            #pragma unroll
            for (int j = 0; j < 4; ++j)
                wmma::load_matrix_sync(bf[j], &Bs[kk * BST + wn * 64 + j * 16], BST);
            #pragma unroll
            for (int i = 0; i < 2; ++i)
                #pragma unroll
                for (int j = 0; j < 4; ++j)
                    wmma::mma_sync(acc[i][j], af[i], bf[j], acc[i][j]);
        }
    }

    // Epilogue: warp writes its 32x64 tile
    #pragma unroll
    for (int i = 0; i < 2; ++i)
        #pragma unroll
        for (int j = 0; j < 4; ++j) {
            float* op = out + ((size_t)b * D1 + d0 + wm * 32 + i * 16) * TLEN
                            + t0 + wn * 64 + j * 16;
            wmma::store_matrix_sync(op, acc[i][j], TLEN, wmma::mem_row_major);
        }
}

extern "C" void kernel_launch(void* const* d_in, const int* in_sizes, int n_in,
                              void* d_out, int out_size)
{
    const float* X    = (const float*)d_in[0];  // [B, CMAX, T]
    const int*   sidx = (const int*)  d_in[1];  // [B]
    const float* W    = (const float*)d_in[2];  // [NS, D1, CMAX]
    float*       out  = (float*)d_out;          // [B, D1, T]

    // Pass 1: fp32 -> fp16 conversion (X once, W once)
    const int64_t total = NXV + NWV;
    const int cblocks = (int)((total + 255) / 256);
    convert_kernel<<<cblocks, 256>>>(X, W);

    // Pass 2: fp16 tensor-core GEMM (static smem, 4 CTAs/SM)
    dim3 grid(TLEN / BN, D1 / BM, BATCH);  // (4, 5, 128)
    sbconv_wmma_kernel<<<grid, 128>>>(sidx, out);
}